// round 9
// baseline (speedup 1.0000x reference)
#include <cuda_runtime.h>
#include <cuda_bf16.h>
#include <math_constants.h>
#include <cstdint>

// ---------------------------------------------------------------- constants
#define NROWS 16384   // B*H*W
#define NE    8192
#define EDIM  256
#define CH    256
#define HWSZ  1024
#define ZQ_ELEMS 4194304
#define LOSS_OFF 4194304
#define IDX_OFF  4194305
#define CAP   64      // shortlist capacity per row

#define SCREEN_SMEM 67584   // 32KB A + 32KB B + 2KB aux

// ---------------------------------------------------------------- scratch
__device__ float    g_zz[NROWS];
__device__ float    g_l1z[NROWS];
__device__ float    g_rmax[NROWS];
__device__ float    g_ee[NE];
__device__ int      g_idx[NROWS];
__device__ double   g_loss;
__device__ unsigned g_maxabse;
__device__ unsigned g_maxL1e;
__device__ unsigned g_rowmin[NROWS];        // order-mapped float
__device__ int      g_ccount[NROWS];
__device__ int      g_clist[NROWS][CAP];
__device__ float    g_Azf[NROWS * EDIM];    // z transposed, fp32 (for rescore)
__device__ int8_t   g_Aq[NROWS * EDIM];     // z int8 (per-row scale)
__device__ int8_t   g_Bq[NE * EDIM];        // codebook int8 (global scale)

// order-preserving float<->uint map (for atomicMin on floats of any sign)
__device__ __forceinline__ unsigned fmap(float f) {
    unsigned u = __float_as_uint(f);
    return (u & 0x80000000u) ? ~u : (u | 0x80000000u);
}
__device__ __forceinline__ float funmap(unsigned u) {
    u = (u & 0x80000000u) ? (u & 0x7FFFFFFFu) : ~u;
    return __uint_as_float(u);
}
__device__ __forceinline__ uint32_t smem_u32(const void* p) {
    uint32_t a;
    asm("{ .reg .u64 t; cvta.to.shared.u64 t, %1; cvt.u32.u64 %0, t; }" : "=r"(a) : "l"(p));
    return a;
}

// ---------------------------------------------------------------------------
__global__ void init_kernel() { g_maxabse = 0; g_maxL1e = 0; g_loss = 0.0; }

// prep: zz (ref rounding: unfused mul+add, ascending) + L1z + rowmax;
//       ee (ref rounding) + global maxabs(e), max L1(e); reset rowmin/ccount
__global__ void prep_kernel(const float* __restrict__ z,
                            const float* __restrict__ cb) {
    int t = blockIdx.x * blockDim.x + threadIdx.x;
    if (t < NROWS) {
        g_rowmin[t] = 0xFFFFFFFFu;
        g_ccount[t] = 0;
        int b = t >> 10, hw = t & 1023;
        const float* p = z + (size_t)b * CH * HWSZ + hw;
        float s = 0.0f, l1 = 0.0f, mx = 0.0f;
#pragma unroll 8
        for (int c = 0; c < CH; c++) {
            float v = p[c * HWSZ];
            s = __fadd_rn(s, __fmul_rn(v, v));   // exact ref rounding for zz
            float av = fabsf(v);
            l1 += av;
            mx = fmaxf(mx, av);
        }
        g_zz[t] = s;
        g_l1z[t] = l1;
        g_rmax[t] = mx;
    } else if (t < NROWS + NE) {
        int k = t - NROWS;
        const float* p = cb + (size_t)k * EDIM;
        float s = 0.0f, l1 = 0.0f, mx = 0.0f;
#pragma unroll 8
        for (int d = 0; d < EDIM; d++) {
            float v = p[d];
            s = __fadd_rn(s, __fmul_rn(v, v));
            float av = fabsf(v);
            l1 += av;
            mx = fmaxf(mx, av);
        }
        g_ee[k] = s;
        atomicMax(&g_maxL1e, __float_as_uint(l1));   // >=0: uint order ok
        atomicMax(&g_maxabse, __float_as_uint(mx));
    }
}

// z: NCHW -> row-major [NROWS][EDIM], fp32
__global__ void split_z_kernel(const float* __restrict__ z) {
    __shared__ float s[32][33];
    int b = blockIdx.z, c0 = blockIdx.y * 32, hw0 = blockIdx.x * 32;
    int tx = threadIdx.x, ty = threadIdx.y;   // block (32, 8)
    const float* zp = z + ((size_t)b * CH + c0) * HWSZ + hw0;
#pragma unroll
    for (int i = 0; i < 4; i++) {
        int cl = ty + i * 8;
        s[cl][tx] = zp[(size_t)cl * HWSZ + tx];
    }
    __syncthreads();
#pragma unroll
    for (int i = 0; i < 4; i++) {
        int hl = ty + i * 8;
        size_t o = (size_t)(b * HWSZ + hw0 + hl) * EDIM + c0 + tx;
        g_Azf[o] = s[tx][hl];
    }
}

// quantize z rows with per-row scale sz = rowmax/127 (vectorized x4)
__global__ void quant_z_kernel() {
    int idx = blockIdx.x * blockDim.x + threadIdx.x;   // 4 elems per thread
    if (idx < NROWS * EDIM / 4) {
        int n = idx >> 6;                               // row (256/4 = 64 per row)
        float inv = 127.0f / fmaxf(g_rmax[n], 1e-30f);
        const float4 v = *(const float4*)(g_Azf + (size_t)idx * 4);
        char4 q;
        q.x = (char)__float2int_rn(v.x * inv);
        q.y = (char)__float2int_rn(v.y * inv);
        q.z = (char)__float2int_rn(v.z * inv);
        q.w = (char)__float2int_rn(v.w * inv);
        *(char4*)(g_Aq + (size_t)idx * 4) = q;
    }
}

// quantize codebook with global scale se = maxabs_e/127 (vectorized x4)
__global__ void quant_cb_kernel(const float* __restrict__ cb) {
    int idx = blockIdx.x * blockDim.x + threadIdx.x;
    if (idx < NE * EDIM / 4) {
        float inv = 127.0f / fmaxf(__uint_as_float(g_maxabse), 1e-30f);
        const float4 v = *(const float4*)(cb + (size_t)idx * 4);
        char4 q;
        q.x = (char)__float2int_rn(v.x * inv);
        q.y = (char)__float2int_rn(v.y * inv);
        q.z = (char)__float2int_rn(v.z * inv);
        q.w = (char)__float2int_rn(v.w * inv);
        *(char4*)(g_Bq + (size_t)idx * 4) = q;
    }
}

// ---------------------------------------------------------------------------
// screening GEMM: int8 mma.sync m16n8k32 + ldmatrix. CTA 128 rows x 128 cands,
// K=256 as 2 chunks of 128 bytes/row, both preloaded via cp.async (occ 2 gives
// cross-CTA load/compute overlap). Int dots are EXACT -> scores deterministic.
// Epilogue: per-row block min -> global running atomicMin -> append cands
// within (running_min + margin); margin = 2*(sz_row*maxL1e + se*L1z_row) + eps
// >= 2*max|screen_score - true_score| -> true winner always appended.
// Smem row = 128B = 8 x 16B chunks, swizzle c ^ (r&7): conflict-free for both
// cp.async stores and ldmatrix 8-row phases. (byte-layout identical to the
// validated bf16 R6 kernel; s8 k32 fragments map to the same addresses.)
// ---------------------------------------------------------------------------
extern __shared__ __align__(16) uint8_t dsmem[];

#define CP_ASYNC(dst, src) \
    asm volatile("cp.async.cg.shared.global [%0], [%1], 16;" :: "r"(dst), "l"(src) : "memory")
#define CP_COMMIT() asm volatile("cp.async.commit_group;" ::: "memory")
#define CP_WAIT(n)  asm volatile("cp.async.wait_group %0;" :: "n"(n) : "memory")
#define LDMX4(r0, r1, r2, r3, addr)                                            \
    asm volatile("ldmatrix.sync.aligned.m8n8.x4.shared.b16 {%0,%1,%2,%3}, [%4];" \
                 : "=r"(r0), "=r"(r1), "=r"(r2), "=r"(r3) : "r"(addr))

__global__ void __launch_bounds__(256, 2) screen_kernel() {
    const int tid = threadIdx.x, lane = tid & 31, wid = tid >> 5;
    const int rowTile  = blockIdx.x & 127;   // fast-varying: first wave covers all rows
    const int candTile = blockIdx.x >> 7;
    const int row0 = rowTile * 128, cand0 = candTile * 128;
    const int wm = wid & 3, wn = wid >> 2;
    const int g = lane >> 2, tg = lane & 3;

    uint8_t*  sAp    = dsmem;                      // 2 chunks x 16KB
    uint8_t*  sBp    = dsmem + 32768;              // 2 chunks x 16KB
    unsigned* s_rmin = (unsigned*)(dsmem + 65536);
    float*    s_thr  = (float*)(dsmem + 66048);
    float*    s_ee   = (float*)(dsmem + 66560);
    float*    s_fac  = (float*)(dsmem + 67072);
    const uint32_t smA = smem_u32(sAp);
    const uint32_t smB = smem_u32(sBp);

    if (tid < 128) {
        s_rmin[tid] = 0xFFFFFFFFu;
        s_ee[tid]   = g_ee[cand0 + tid];
        float se  = __uint_as_float(g_maxabse) * (1.0f / 127.0f);
        float szr = g_rmax[row0 + tid] * (1.0f / 127.0f);
        s_fac[tid] = 2.0f * szr * se;       // dequant factor for this row
    }

    // ---- per-lane ldmatrix address precompute (sel: matrix within x4)
    const int rl  = lane & 7;
    const int sel = lane >> 3;
    uint32_t aOff[2]; uint32_t aM7[2];
#pragma unroll
    for (int mf = 0; mf < 2; mf++) {
        int row = wm * 32 + mf * 16 + (sel & 1) * 8 + rl;
        aOff[mf] = (uint32_t)(row * 128);
        aM7[mf]  = (uint32_t)(row & 7);
    }
    const uint32_t aCs = (uint32_t)(sel >> 1);
    uint32_t bOff[4]; uint32_t bM7[4];
#pragma unroll
    for (int p = 0; p < 4; p++) {
        int row = wn * 64 + p * 16 + (sel >> 1) * 8 + rl;
        bOff[p] = (uint32_t)(row * 128);
        bM7[p]  = (uint32_t)(row & 7);
    }
    const uint32_t bCs = (uint32_t)(sel & 1);

    int acc[2][8][4];
#pragma unroll
    for (int mf = 0; mf < 2; mf++)
#pragma unroll
        for (int nf = 0; nf < 8; nf++)
#pragma unroll
            for (int q = 0; q < 4; q++) acc[mf][nf][q] = 0;

#define LOAD_CHUNK(stage, kc)                                                  \
    {                                                                          \
        _Pragma("unroll")                                                      \
        for (int it = 0; it < 4; it++) {                                       \
            int u = tid + it * 256;                                            \
            int r = u >> 3, c = u & 7;                                         \
            uint32_t so = (uint32_t)((stage) * 16384 + r * 128 + ((c ^ (r & 7)) << 4)); \
            CP_ASYNC(smA + so, g_Aq + (size_t)(row0 + r) * EDIM + (kc) * 128 + c * 16);  \
            CP_ASYNC(smB + so, g_Bq + (size_t)(cand0 + r) * EDIM + (kc) * 128 + c * 16); \
        }                                                                      \
        CP_COMMIT();                                                           \
    }

#define MMA_CHUNK(stage)                                                       \
    {                                                                          \
        const uint32_t bufA = smA + (stage) * 16384;                           \
        const uint32_t bufB = smB + (stage) * 16384;                           \
        _Pragma("unroll")                                                      \
        for (int ks = 0; ks < 4; ks++) {   /* k32 steps within 128-byte chunk */ \
            uint32_t a[2][4], b[8][2];                                         \
            const uint32_t ca  = (uint32_t)(2 * ks) + aCs;                     \
            const uint32_t cbk = (uint32_t)(2 * ks) + bCs;                     \
            _Pragma("unroll")                                                  \
            for (int mf = 0; mf < 2; mf++) {                                   \
                uint32_t addr = bufA + aOff[mf] + (((ca ^ aM7[mf]) & 7u) << 4); \
                LDMX4(a[mf][0], a[mf][1], a[mf][2], a[mf][3], addr);           \
            }                                                                  \
            _Pragma("unroll")                                                  \
            for (int p = 0; p < 4; p++) {                                      \
                uint32_t addr = bufB + bOff[p] + (((cbk ^ bM7[p]) & 7u) << 4); \
                LDMX4(b[2*p][0], b[2*p][1], b[2*p+1][0], b[2*p+1][1], addr);   \
            }                                                                  \
            _Pragma("unroll")                                                  \
            for (int mf = 0; mf < 2; mf++)                                     \
                _Pragma("unroll")                                              \
                for (int nf = 0; nf < 8; nf++)                                 \
                    asm volatile(                                              \
                        "mma.sync.aligned.m16n8k32.row.col.s32.s8.s8.s32 "     \
                        "{%0,%1,%2,%3},{%4,%5,%6,%7},{%8,%9},{%0,%1,%2,%3};"   \
                        : "+r"(acc[mf][nf][0]), "+r"(acc[mf][nf][1]),          \
                          "+r"(acc[mf][nf][2]), "+r"(acc[mf][nf][3])           \
                        : "r"(a[mf][0]), "r"(a[mf][1]), "r"(a[mf][2]), "r"(a[mf][3]), \
                          "r"(b[nf][0]), "r"(b[nf][1]));                       \
        }                                                                      \
    }

    // preload both K-chunks; occ-2 cross-CTA overlap hides the latency
    LOAD_CHUNK(0, 0);
    LOAD_CHUNK(1, 1);

    CP_WAIT(1); __syncthreads();      // chunk 0 ready
    MMA_CHUNK(0);
    CP_WAIT(0); __syncthreads();      // chunk 1 ready
    MMA_CHUNK(1);

    // ---- epilogue pass 1: per-row block min (int dot -> exact fp32 score)
#pragma unroll
    for (int mf = 0; mf < 2; mf++)
#pragma unroll
        for (int h = 0; h < 2; h++) {
            int rlo = wm * 32 + mf * 16 + g + h * 8;
            float fac = s_fac[rlo];
            float rmin = CUDART_INF_F;
#pragma unroll
            for (int nf = 0; nf < 8; nf++) {
                int cl = wn * 64 + nf * 8 + 2 * tg;
                float s0 = s_ee[cl]     - fac * __int2float_rn(acc[mf][nf][h * 2 + 0]);
                float s1 = s_ee[cl + 1] - fac * __int2float_rn(acc[mf][nf][h * 2 + 1]);
                rmin = fminf(rmin, fminf(s0, s1));
            }
            atomicMin(&s_rmin[rlo], fmap(rmin));
        }
    __syncthreads();
    // fold into global running min, compute per-row threshold
    if (tid < 128) {
        unsigned mine = s_rmin[tid];
        unsigned old  = atomicMin(&g_rowmin[row0 + tid], mine);
        float gmin = fminf(funmap(old), funmap(mine));
        float se  = __uint_as_float(g_maxabse) * (1.0f / 127.0f);
        float szr = g_rmax[row0 + tid] * (1.0f / 127.0f);
        float marg = 2.0f * (szr * __uint_as_float(g_maxL1e) + se * g_l1z[row0 + tid]) + 1e-5f;
        s_thr[tid] = gmin + marg;
    }
    __syncthreads();
    // ---- epilogue pass 2: append candidates under threshold
#pragma unroll
    for (int mf = 0; mf < 2; mf++)
#pragma unroll
        for (int h = 0; h < 2; h++) {
            int rlo = wm * 32 + mf * 16 + g + h * 8;
            int grow = row0 + rlo;
            float fac = s_fac[rlo];
            float thr = s_thr[rlo];
#pragma unroll
            for (int nf = 0; nf < 8; nf++) {
                int cl = wn * 64 + nf * 8 + 2 * tg;
                float s0 = s_ee[cl]     - fac * __int2float_rn(acc[mf][nf][h * 2 + 0]);
                float s1 = s_ee[cl + 1] - fac * __int2float_rn(acc[mf][nf][h * 2 + 1]);
                if (s0 <= thr) {
                    int p = atomicAdd(&g_ccount[grow], 1);
                    if (p < CAP) g_clist[grow][p] = cand0 + cl;
                }
                if (s1 <= thr) {
                    int p = atomicAdd(&g_ccount[grow], 1);
                    if (p < CAP) g_clist[grow][p] = cand0 + cl + 1;
                }
            }
        }
}

// ---------------------------------------------------------------------------
// rescore: exact fp32 (ascending-d fmaf chain) + reference rounding,
// lexicographic (d, idx) min -> first-index tie behavior. Warp per row.
// ---------------------------------------------------------------------------
__global__ void rescore_kernel(const float* __restrict__ cb) {
    int w = (blockIdx.x * blockDim.x + threadIdx.x) >> 5;
    int lane = threadIdx.x & 31;
    if (w >= NROWS) return;
    int cnt = g_ccount[w];
    float zzv = g_zz[w];
    const float* zr = g_Azf + (size_t)w * EDIM;
    float bd = CUDART_INF_F;
    int bi = 0x7FFFFFFF;
    if (cnt <= CAP) {
        for (int sl = lane; sl < cnt; sl += 32) {
            int k = g_clist[w][sl];
            const float* er = cb + (size_t)k * EDIM;
            float s = 0.0f;
#pragma unroll 8
            for (int d = 0; d < EDIM; d++) s = fmaf(zr[d], er[d], s);
            float t = __fadd_rn(zzv, g_ee[k]);
            float dv = __fadd_rn(t, -2.0f * s);
            if (dv < bd || (dv == bd && k < bi)) { bd = dv; bi = k; }
        }
    } else {  // overflow (rare): exact scan of all candidates
        for (int k = lane; k < NE; k += 32) {
            const float* er = cb + (size_t)k * EDIM;
            float s = 0.0f;
#pragma unroll 8
            for (int d = 0; d < EDIM; d++) s = fmaf(zr[d], er[d], s);
            float t = __fadd_rn(zzv, g_ee[k]);
            float dv = __fadd_rn(t, -2.0f * s);
            if (dv < bd || (dv == bd && k < bi)) { bd = dv; bi = k; }
        }
    }
#pragma unroll
    for (int o = 16; o; o >>= 1) {
        float od = __shfl_xor_sync(0xFFFFFFFFu, bd, o);
        int   oi = __shfl_xor_sync(0xFFFFFFFFu, bi, o);
        if (od < bd || (od == bd && oi < bi)) { bd = od; bi = oi; }
    }
    if (lane == 0) g_idx[w] = bi;
}

// ---------------------------------------------------------------------------
// output: z_q gather + loss partial sums
// ---------------------------------------------------------------------------
__global__ void output_kernel(const float* __restrict__ z,
                              const float* __restrict__ cb,
                              float* __restrict__ out) {
    float lsum = 0.0f;
    int stride = gridDim.x * blockDim.x;
    for (int o = blockIdx.x * blockDim.x + threadIdx.x; o < ZQ_ELEMS; o += stride) {
        int bq = o >> 18;
        int c  = (o >> 10) & 255;
        int hw = o & 1023;
        int n  = (bq << 10) | hw;
        int id = g_idx[n];
        float q  = __ldg(&cb[(size_t)id * EDIM + c]);
        float zp = z[o];
        out[o] = q;
        float dd = q - zp;
        lsum += dd * dd;
    }
    __shared__ float red[256];
    red[threadIdx.x] = lsum;
    __syncthreads();
    for (int s = 128; s > 0; s >>= 1) {
        if (threadIdx.x < s) red[threadIdx.x] += red[threadIdx.x + s];
        __syncthreads();
    }
    if (threadIdx.x == 0) atomicAdd(&g_loss, (double)red[0]);
}

__global__ void finalize_kernel(float* __restrict__ out, int out_size) {
    int t = blockIdx.x * blockDim.x + threadIdx.x;
    if (t == 0 && out_size > LOSS_OFF) {
        float m = (float)(g_loss * (1.0 / 4194304.0));
        out[LOSS_OFF] = __fadd_rn(m, 0.25f * m);
    }
    if (t < NROWS && out_size >= IDX_OFF + NROWS) {
        out[IDX_OFF + t] = (float)g_idx[t];
    }
}

// ---------------------------------------------------------------------------
extern "C" void kernel_launch(void* const* d_in, const int* in_sizes, int n_in,
                              void* d_out, int out_size) {
    const float* z  = (const float*)d_in[0];
    const float* cb = (const float*)d_in[1];
    float* out = (float*)d_out;

    cudaFuncSetAttribute(screen_kernel,
                         cudaFuncAttributeMaxDynamicSharedMemorySize, SCREEN_SMEM);

    init_kernel<<<1, 1>>>();
    prep_kernel<<<(NROWS + NE + 255) / 256, 256>>>(z, cb);
    split_z_kernel<<<dim3(HWSZ / 32, CH / 32, 16), dim3(32, 8)>>>(z);
    quant_z_kernel<<<(NROWS * EDIM / 4 + 255) / 256, 256>>>();
    quant_cb_kernel<<<(NE * EDIM / 4 + 255) / 256, 256>>>(cb);
    screen_kernel<<<128 * 64, 256, SCREEN_SMEM>>>();
    rescore_kernel<<<(NROWS * 32) / 256, 256>>>(cb);
    output_kernel<<<1024, 256>>>(z, cb, out);
    finalize_kernel<<<(NROWS + 255) / 256, 256>>>(out, out_size);
}

// round 10
// speedup vs baseline: 9.4114x; 9.4114x over previous
#include <cuda_runtime.h>
#include <cuda_fp16.h>
#include <math_constants.h>
#include <cstdint>

// ---------------------------------------------------------------- constants
#define NROWS 16384   // B*H*W
#define NE    8192
#define EDIM  256
#define CH    256
#define HWSZ  1024
#define ZQ_ELEMS 4194304
#define LOSS_OFF 4194304
#define IDX_OFF  4194305
#define CAP   64      // shortlist capacity per row

#define SCREEN_SMEM 99840

// ---------------------------------------------------------------- scratch
__device__ float    g_zz[NROWS];
__device__ float    g_ee[NE];
__device__ int      g_idx[NROWS];
__device__ double   g_loss;
__device__ unsigned g_maxee;
__device__ unsigned g_rowmin[NROWS];        // order-mapped float
__device__ int      g_ccount[NROWS];
__device__ int      g_clist[NROWS][CAP];
__device__ float    g_Azf[NROWS * EDIM];    // z transposed, fp32 (for rescore)
__device__ uint16_t g_Ah[NROWS * EDIM];     // z transposed, fp16
__device__ uint16_t g_Bh[NE * EDIM];        // codebook, fp16

// order-preserving float<->uint map (for atomicMin on floats of any sign)
__device__ __forceinline__ unsigned fmap(float f) {
    unsigned u = __float_as_uint(f);
    return (u & 0x80000000u) ? ~u : (u | 0x80000000u);
}
__device__ __forceinline__ float funmap(unsigned u) {
    u = (u & 0x80000000u) ? (u & 0x7FFFFFFFu) : ~u;
    return __uint_as_float(u);
}
__device__ __forceinline__ uint32_t smem_u32(const void* p) {
    uint32_t a;
    asm("{ .reg .u64 t; cvta.to.shared.u64 t, %1; cvt.u32.u64 %0, t; }" : "=r"(a) : "l"(p));
    return a;
}

// ---------------------------------------------------------------------------
__global__ void init_kernel() { g_maxee = 0; g_loss = 0.0; }

// prep: zz (ref rounding: unfused mul+add, ascending), ee (+ maxee),
//       reset rowmin/ccount
__global__ void prep_kernel(const float* __restrict__ z,
                            const float* __restrict__ cb) {
    int t = blockIdx.x * blockDim.x + threadIdx.x;
    if (t < NROWS) {
        g_rowmin[t] = 0xFFFFFFFFu;
        g_ccount[t] = 0;
        int b = t >> 10, hw = t & 1023;
        const float* p = z + (size_t)b * CH * HWSZ + hw;
        float s = 0.0f;
#pragma unroll 8
        for (int c = 0; c < CH; c++) {
            float v = p[c * HWSZ];
            s = __fadd_rn(s, __fmul_rn(v, v));
        }
        g_zz[t] = s;
    } else if (t < NROWS + NE) {
        int k = t - NROWS;
        const float* p = cb + (size_t)k * EDIM;
        float s = 0.0f;
#pragma unroll 8
        for (int d = 0; d < EDIM; d++) {
            float v = p[d];
            s = __fadd_rn(s, __fmul_rn(v, v));
        }
        g_ee[k] = s;
        atomicMax(&g_maxee, __float_as_uint(s));   // s >= 0: uint order ok
    }
}

// codebook -> fp16
__global__ void split_cb_kernel(const float* __restrict__ cb) {
    int i = blockIdx.x * blockDim.x + threadIdx.x;
    if (i < NE * EDIM) {
        __half h = __float2half_rn(cb[i]);
        g_Bh[i] = *(uint16_t*)&h;
    }
}

// z: NCHW -> row-major [NROWS][EDIM], fp32 + fp16
__global__ void split_z_kernel(const float* __restrict__ z) {
    __shared__ float s[32][33];
    int b = blockIdx.z, c0 = blockIdx.y * 32, hw0 = blockIdx.x * 32;
    int tx = threadIdx.x, ty = threadIdx.y;   // block (32, 8)
    const float* zp = z + ((size_t)b * CH + c0) * HWSZ + hw0;
#pragma unroll
    for (int i = 0; i < 4; i++) {
        int cl = ty + i * 8;
        s[cl][tx] = zp[(size_t)cl * HWSZ + tx];
    }
    __syncthreads();
#pragma unroll
    for (int i = 0; i < 4; i++) {
        int hl = ty + i * 8;
        size_t o = (size_t)(b * HWSZ + hw0 + hl) * EDIM + c0 + tx;
        float x = s[tx][hl];
        g_Azf[o] = x;
        __half h = __float2half_rn(x);
        g_Ah[o] = *(uint16_t*)&h;
    }
}

// ---------------------------------------------------------------------------
// screening GEMM: fp16 mma.sync (f16 accumulate) + ldmatrix + cp.async
// 3-stage pipeline. CTA 128 rows x 128 cands, K=256 in 4 chunks of 64.
// Epilogue: per-row block min -> global running atomicMin -> append cands
// within (running_min + margin); margin covers fp16 input quant + fp16 acc
// rounding (worst case ~3.1e-4 < 0.032*sqrt(zz)*sqrt(maxee) ~ 5.8e-4).
// Smem row = 64 fp16 = 128B; 16B-chunk swizzle c ^ (r&7): conflict-free for
// cp.async stores and ldmatrix 8-row phases.
// ---------------------------------------------------------------------------
extern __shared__ __align__(16) uint8_t dsmem[];

#define CP_ASYNC(dst, src) \
    asm volatile("cp.async.cg.shared.global [%0], [%1], 16;" :: "r"(dst), "l"(src) : "memory")
#define CP_COMMIT() asm volatile("cp.async.commit_group;" ::: "memory")
#define CP_WAIT(n)  asm volatile("cp.async.wait_group %0;" :: "n"(n) : "memory")
#define LDMX4(r0, r1, r2, r3, addr)                                            \
    asm volatile("ldmatrix.sync.aligned.m8n8.x4.shared.b16 {%0,%1,%2,%3}, [%4];" \
                 : "=r"(r0), "=r"(r1), "=r"(r2), "=r"(r3) : "r"(addr))

__global__ void __launch_bounds__(256, 2) screen_kernel() {
    const int tid = threadIdx.x, lane = tid & 31, wid = tid >> 5;
    const int rowTile  = blockIdx.x & 127;   // fast-varying: first wave covers all rows
    const int candTile = blockIdx.x >> 7;
    const int row0 = rowTile * 128, cand0 = candTile * 128;
    const int wm = wid & 3, wn = wid >> 2;
    const int g = lane >> 2, tg = lane & 3;

    uint8_t*  sAp    = dsmem;                      // 3 stages x 16KB
    uint8_t*  sBp    = dsmem + 49152;              // 3 stages x 16KB
    unsigned* s_rmin = (unsigned*)(dsmem + 98304);
    float*    s_thr  = (float*)(dsmem + 98816);
    float*    s_ee   = (float*)(dsmem + 99328);
    const uint32_t smA = smem_u32(sAp);
    const uint32_t smB = smem_u32(sBp);

    if (tid < 128) {
        s_rmin[tid] = 0xFFFFFFFFu;
        s_ee[tid]   = g_ee[cand0 + tid];
    }

    // ---- per-lane ldmatrix address precompute
    const int rl  = lane & 7;
    const int sel = lane >> 3;
    uint32_t aOff[2]; uint32_t aM7[2];
#pragma unroll
    for (int mf = 0; mf < 2; mf++) {
        int row = wm * 32 + mf * 16 + (sel & 1) * 8 + rl;
        aOff[mf] = (uint32_t)(row * 128);
        aM7[mf]  = (uint32_t)(row & 7);
    }
    const uint32_t aCs = (uint32_t)(sel >> 1);
    uint32_t bOff[4]; uint32_t bM7[4];
#pragma unroll
    for (int p = 0; p < 4; p++) {
        int row = wn * 64 + p * 16 + (sel >> 1) * 8 + rl;
        bOff[p] = (uint32_t)(row * 128);
        bM7[p]  = (uint32_t)(row & 7);
    }
    const uint32_t bCs = (uint32_t)(sel & 1);

    // fp16 accumulators: 2 x .f16x2 regs per mma tile
    uint32_t acc[2][8][2];
#pragma unroll
    for (int mf = 0; mf < 2; mf++)
#pragma unroll
        for (int nf = 0; nf < 8; nf++) {
            acc[mf][nf][0] = 0u;
            acc[mf][nf][1] = 0u;
        }

#define LOAD_CHUNK(stage, kc)                                                  \
    {                                                                          \
        _Pragma("unroll")                                                      \
        for (int it = 0; it < 4; it++) {                                       \
            int u = tid + it * 256;                                            \
            int r = u >> 3, c = u & 7;                                         \
            uint32_t so = (uint32_t)((stage) * 16384 + r * 128 + ((c ^ (r & 7)) << 4)); \
            CP_ASYNC(smA + so, g_Ah + (size_t)(row0 + r) * EDIM + (kc) * 64 + c * 8);  \
            CP_ASYNC(smB + so, g_Bh + (size_t)(cand0 + r) * EDIM + (kc) * 64 + c * 8); \
        }                                                                      \
        CP_COMMIT();                                                           \
    }

#define MMA_CHUNK(stage)                                                       \
    {                                                                          \
        const uint32_t bufA = smA + (stage) * 16384;                           \
        const uint32_t bufB = smB + (stage) * 16384;                           \
        _Pragma("unroll")                                                      \
        for (int ks = 0; ks < 4; ks++) {                                       \
            uint32_t a[2][4], b[8][2];                                         \
            const uint32_t ca  = (uint32_t)(2 * ks) + aCs;                     \
            const uint32_t cbk = (uint32_t)(2 * ks) + bCs;                     \
            _Pragma("unroll")                                                  \
            for (int mf = 0; mf < 2; mf++) {                                   \
                uint32_t addr = bufA + aOff[mf] + (((ca ^ aM7[mf]) & 7u) << 4); \
                LDMX4(a[mf][0], a[mf][1], a[mf][2], a[mf][3], addr);           \
            }                                                                  \
            _Pragma("unroll")                                                  \
            for (int p = 0; p < 4; p++) {                                      \
                uint32_t addr = bufB + bOff[p] + (((cbk ^ bM7[p]) & 7u) << 4); \
                LDMX4(b[2*p][0], b[2*p][1], b[2*p+1][0], b[2*p+1][1], addr);   \
            }                                                                  \
            _Pragma("unroll")                                                  \
            for (int mf = 0; mf < 2; mf++)                                     \
                _Pragma("unroll")                                              \
                for (int nf = 0; nf < 8; nf++)                                 \
                    asm volatile(                                              \
                        "mma.sync.aligned.m16n8k16.row.col.f16.f16.f16.f16 "   \
                        "{%0,%1},{%2,%3,%4,%5},{%6,%7},{%0,%1};"               \
                        : "+r"(acc[mf][nf][0]), "+r"(acc[mf][nf][1])           \
                        : "r"(a[mf][0]), "r"(a[mf][1]), "r"(a[mf][2]), "r"(a[mf][3]), \
                          "r"(b[nf][0]), "r"(b[nf][1]));                       \
        }                                                                      \
    }

    // 3-stage pipeline over 4 K-chunks
    LOAD_CHUNK(0, 0);
    LOAD_CHUNK(1, 1);
    LOAD_CHUNK(2, 2);

    CP_WAIT(2); __syncthreads();      // chunk 0 ready
    MMA_CHUNK(0);
    __syncthreads();                  // stage 0 free
    LOAD_CHUNK(0, 3);

    CP_WAIT(2); __syncthreads();      // chunk 1 ready
    MMA_CHUNK(1);

    CP_WAIT(1); __syncthreads();      // chunk 2 ready
    MMA_CHUNK(2);

    CP_WAIT(0); __syncthreads();      // chunk 3 ready (in stage 0)
    MMA_CHUNK(0);

    // ---- epilogue pass 1: per-row block min
#pragma unroll
    for (int mf = 0; mf < 2; mf++)
#pragma unroll
        for (int h = 0; h < 2; h++) {
            int rlo = wm * 32 + mf * 16 + g + h * 8;
            float rmin = CUDART_INF_F;
#pragma unroll
            for (int nf = 0; nf < 8; nf++) {
                int cl = wn * 64 + nf * 8 + 2 * tg;
                float2 dv = __half22float2(*(__half2*)&acc[mf][nf][h]);
                float s0 = s_ee[cl]     - 2.0f * dv.x;
                float s1 = s_ee[cl + 1] - 2.0f * dv.y;
                rmin = fminf(rmin, fminf(s0, s1));
            }
            atomicMin(&s_rmin[rlo], fmap(rmin));
        }
    __syncthreads();
    // fold into global running min, compute threshold
    if (tid < 128) {
        unsigned mine = s_rmin[tid];
        unsigned old  = atomicMin(&g_rowmin[row0 + tid], mine);
        float gmin = fminf(funmap(old), funmap(mine));
        float sqee = sqrtf(__uint_as_float(g_maxee));
        s_thr[tid] = gmin + 0.032f * sqrtf(g_zz[row0 + tid]) * sqee + 2e-5f;
    }
    __syncthreads();
    // ---- epilogue pass 2: append candidates under threshold
#pragma unroll
    for (int mf = 0; mf < 2; mf++)
#pragma unroll
        for (int h = 0; h < 2; h++) {
            int rlo = wm * 32 + mf * 16 + g + h * 8;
            int grow = row0 + rlo;
            float thr = s_thr[rlo];
#pragma unroll
            for (int nf = 0; nf < 8; nf++) {
                int cl = wn * 64 + nf * 8 + 2 * tg;
                float2 dv = __half22float2(*(__half2*)&acc[mf][nf][h]);
                float s0 = s_ee[cl]     - 2.0f * dv.x;
                float s1 = s_ee[cl + 1] - 2.0f * dv.y;
                if (s0 <= thr) {
                    int p = atomicAdd(&g_ccount[grow], 1);
                    if (p < CAP) g_clist[grow][p] = cand0 + cl;
                }
                if (s1 <= thr) {
                    int p = atomicAdd(&g_ccount[grow], 1);
                    if (p < CAP) g_clist[grow][p] = cand0 + cl + 1;
                }
            }
        }
}

// ---------------------------------------------------------------------------
// rescore: exact fp32 (ascending-d fmaf chain) + reference rounding,
// lexicographic (d, idx) min -> first-index tie behavior. Warp per row.
// ---------------------------------------------------------------------------
__global__ void rescore_kernel(const float* __restrict__ cb) {
    int w = (blockIdx.x * blockDim.x + threadIdx.x) >> 5;
    int lane = threadIdx.x & 31;
    if (w >= NROWS) return;
    int cnt = g_ccount[w];
    float zzv = g_zz[w];
    const float* zr = g_Azf + (size_t)w * EDIM;
    float bd = CUDART_INF_F;
    int bi = 0x7FFFFFFF;
    if (cnt <= CAP) {
        for (int sl = lane; sl < cnt; sl += 32) {
            int k = g_clist[w][sl];
            const float* er = cb + (size_t)k * EDIM;
            float s = 0.0f;
#pragma unroll 8
            for (int d = 0; d < EDIM; d++) s = fmaf(zr[d], er[d], s);
            float t = __fadd_rn(zzv, g_ee[k]);
            float dv = __fadd_rn(t, -2.0f * s);
            if (dv < bd || (dv == bd && k < bi)) { bd = dv; bi = k; }
        }
    } else {  // overflow (rare): exact scan of all candidates
        for (int k = lane; k < NE; k += 32) {
            const float* er = cb + (size_t)k * EDIM;
            float s = 0.0f;
#pragma unroll 8
            for (int d = 0; d < EDIM; d++) s = fmaf(zr[d], er[d], s);
            float t = __fadd_rn(zzv, g_ee[k]);
            float dv = __fadd_rn(t, -2.0f * s);
            if (dv < bd || (dv == bd && k < bi)) { bd = dv; bi = k; }
        }
    }
#pragma unroll
    for (int o = 16; o; o >>= 1) {
        float od = __shfl_xor_sync(0xFFFFFFFFu, bd, o);
        int   oi = __shfl_xor_sync(0xFFFFFFFFu, bi, o);
        if (od < bd || (od == bd && oi < bi)) { bd = od; bi = oi; }
    }
    if (lane == 0) g_idx[w] = bi;
}

// ---------------------------------------------------------------------------
// output: z_q gather + loss partial sums
// ---------------------------------------------------------------------------
__global__ void output_kernel(const float* __restrict__ z,
                              const float* __restrict__ cb,
                              float* __restrict__ out) {
    float lsum = 0.0f;
    int stride = gridDim.x * blockDim.x;
    for (int o = blockIdx.x * blockDim.x + threadIdx.x; o < ZQ_ELEMS; o += stride) {
        int bq = o >> 18;
        int c  = (o >> 10) & 255;
        int hw = o & 1023;
        int n  = (bq << 10) | hw;
        int id = g_idx[n];
        float q  = __ldg(&cb[(size_t)id * EDIM + c]);
        float zp = z[o];
        out[o] = q;
        float dd = q - zp;
        lsum += dd * dd;
    }
    __shared__ float red[256];
    red[threadIdx.x] = lsum;
    __syncthreads();
    for (int s = 128; s > 0; s >>= 1) {
        if (threadIdx.x < s) red[threadIdx.x] += red[threadIdx.x + s];
        __syncthreads();
    }
    if (threadIdx.x == 0) atomicAdd(&g_loss, (double)red[0]);
}

__global__ void finalize_kernel(float* __restrict__ out, int out_size) {
    int t = blockIdx.x * blockDim.x + threadIdx.x;
    if (t == 0 && out_size > LOSS_OFF) {
        float m = (float)(g_loss * (1.0 / 4194304.0));
        out[LOSS_OFF] = __fadd_rn(m, 0.25f * m);
    }
    if (t < NROWS && out_size >= IDX_OFF + NROWS) {
        out[IDX_OFF + t] = (float)g_idx[t];
    }
}

// ---------------------------------------------------------------------------
extern "C" void kernel_launch(void* const* d_in, const int* in_sizes, int n_in,
                              void* d_out, int out_size) {
    const float* z  = (const float*)d_in[0];
    const float* cb = (const float*)d_in[1];
    float* out = (float*)d_out;

    cudaFuncSetAttribute(screen_kernel,
                         cudaFuncAttributeMaxDynamicSharedMemorySize, SCREEN_SMEM);

    init_kernel<<<1, 1>>>();
    prep_kernel<<<(NROWS + NE + 255) / 256, 256>>>(z, cb);
    split_cb_kernel<<<(NE * EDIM) / 256, 256>>>(cb);
    split_z_kernel<<<dim3(HWSZ / 32, CH / 32, 16), dim3(32, 8)>>>(z);
    screen_kernel<<<128 * 64, 256, SCREEN_SMEM>>>();
    rescore_kernel<<<(NROWS * 32) / 256, 256>>>(cb);
    output_kernel<<<1024, 256>>>(z, cb, out);
    finalize_kernel<<<(NROWS + 255) / 256, 256>>>(out, out_size);
}